// round 3
// baseline (speedup 1.0000x reference)
#include <cuda_runtime.h>
#include <cuda_bf16.h>

#define NN 50000
#define KK 17
#define DIN 128
#define DOUT 64

// Scratch for projected features xp = x @ W : [N, 64] fp32 = 12.8 MB (fits in L2)
__device__ float g_xp[(size_t)NN * DOUT];

// ---------------------------------------------------------------------------
// Kernel 1: xp = x @ W   (fp32). Tile M=128, N=64(all), K chunked by 32.
// 256 threads: thread handles 8 rows x 4 cols = 32 accumulators. (at FFMA floor)
// ---------------------------------------------------------------------------
__global__ void __launch_bounds__(256) gemm_kernel(
    const float* __restrict__ x, const float* __restrict__ wm)
{
    __shared__ float xs[128][32];
    __shared__ float ws[32][64];

    const int tid  = threadIdx.x;
    const int row0 = blockIdx.x * 128;
    const int c0   = (tid & 15) * 4;
    const int r0   = (tid >> 4) * 8;

    float acc[8][4];
#pragma unroll
    for (int i = 0; i < 8; i++)
#pragma unroll
        for (int j = 0; j < 4; j++) acc[i][j] = 0.f;

    for (int k0 = 0; k0 < DIN; k0 += 32) {
#pragma unroll
        for (int i = 0; i < 4; i++) {
            const int f4 = tid + 256 * i;
            const int r  = f4 >> 3;
            const int cc = (f4 & 7) * 4;
            int gr = row0 + r;
            if (gr > NN - 1) gr = NN - 1;
            const float4 v = *(const float4*)(x + (size_t)gr * DIN + k0 + cc);
            *(float4*)&xs[r][cc] = v;
        }
#pragma unroll
        for (int i = 0; i < 2; i++) {
            const int f4 = tid + 256 * i;
            const int r  = f4 >> 4;
            const int cc = (f4 & 15) * 4;
            const float4 v = *(const float4*)(wm + (size_t)(k0 + r) * DOUT + cc);
            *(float4*)&ws[r][cc] = v;
        }
        __syncthreads();

#pragma unroll
        for (int kk = 0; kk < 32; kk += 2) {
            const float4 w0 = *(const float4*)&ws[kk][c0];
            const float4 w1 = *(const float4*)&ws[kk + 1][c0];
#pragma unroll
            for (int i = 0; i < 8; i++) {
                const float2 xv = *(const float2*)&xs[r0 + i][kk];
                acc[i][0] += xv.x * w0.x;
                acc[i][1] += xv.x * w0.y;
                acc[i][2] += xv.x * w0.z;
                acc[i][3] += xv.x * w0.w;
                acc[i][0] += xv.y * w1.x;
                acc[i][1] += xv.y * w1.y;
                acc[i][2] += xv.y * w1.z;
                acc[i][3] += xv.y * w1.w;
            }
        }
        __syncthreads();
    }

#pragma unroll
    for (int i = 0; i < 8; i++) {
        const int gr = row0 + r0 + i;
        if (gr < NN) {
            float4 v;
            v.x = acc[i][0]; v.y = acc[i][1]; v.z = acc[i][2]; v.w = acc[i][3];
            *(float4*)&g_xp[(size_t)gr * DOUT + c0] = v;
        }
    }
}

// ---------------------------------------------------------------------------
// Kernel 2: weighted per-dimension median via truncated Batcher odd-even
// sorting network (N=32 net restricted to 17 wires -> 86 compare-exchanges),
// then cumsum walk to find first prefix >= 0.5*total (exactly matches the
// reference's argsort+cumsum+argmax for distinct values).
// One thread per (node, dim); 128-thread blocks = 2 nodes.
// All ops are lat-4 dataflow (FSETP-as-data + FSEL/FMNMX), no pred guards.
// ---------------------------------------------------------------------------
__global__ void __launch_bounds__(128) median_kernel(
    const int*   __restrict__ col,
    const float* __restrict__ ew,
    const float* __restrict__ bias,
    float*       __restrict__ out)
{
    __shared__ float swt[2][KK];
    __shared__ int   soff[2][KK];

    const int tid   = threadIdx.x;
    const int local = tid >> 6;
    const int d     = tid & 63;
    const int node  = blockIdx.x * 2 + local;

    if (d < KK) {
        swt[local][d]  = ew[node * KK + d];
        soff[local][d] = col[node * KK + d] * DOUT;
    }
    __syncthreads();

    const float* __restrict__ xpd = g_xp + d;

    float w[KK], v[KK];
#pragma unroll
    for (int j = 0; j < KK; j++) {
        w[j] = swt[local][j];
        v[j] = __ldg(xpd + soff[local][j]);
    }

    float total = 0.f;
#pragma unroll
    for (int j = 0; j < KK; j++) total += w[j];
    const float hf = 0.5f * total;

    // Batcher odd-even mergesort network for 32 wires, truncated to 17.
    // Dropped CEs only touch wires >= 17 (virtual +inf), so truncation is a
    // valid sorting network for 17 elements. ~86 CEs, fully unrolled.
#pragma unroll
    for (int p = 1; p < 32; p <<= 1) {
#pragma unroll
        for (int k = p; k >= 1; k >>= 1) {
#pragma unroll
            for (int j = k % p; j + k < 32; j += 2 * k) {
#pragma unroll
                for (int i = 0; i < k; i++) {
                    const int a = i + j;
                    const int b = i + j + k;
                    if (b < KK && (a / (2 * p)) == (b / (2 * p))) {
                        const bool  sw = v[b] < v[a];
                        const float vl = fminf(v[a], v[b]);
                        const float vh = fmaxf(v[a], v[b]);
                        const float wl = sw ? w[b] : w[a];
                        const float wh = sw ? w[a] : w[b];
                        v[a] = vl; v[b] = vh;
                        w[a] = wl; w[b] = wh;
                    }
                }
            }
        }
    }

    // First sorted element whose cumulative weight reaches half-total.
    float cum = w[0];
    float med = v[0];
#pragma unroll
    for (int j = 1; j < KK; j++) {
        med  = (cum < hf) ? v[j] : med;
        cum += w[j];
    }

    out[(size_t)node * DOUT + d] = total * med + __ldg(&bias[d]);
}

// ---------------------------------------------------------------------------
// Inputs: x[N,128] f32, edge_index[2,E] i32, edge_weight[E] f32,
//         weight[128,64] f32, bias[64] f32. Output: [N,64] f32.
// ---------------------------------------------------------------------------
extern "C" void kernel_launch(void* const* d_in, const int* in_sizes, int n_in,
                              void* d_out, int out_size)
{
    const float* x    = (const float*)d_in[0];
    const int*   ei   = (const int*)  d_in[1];
    const float* ew   = (const float*)d_in[2];
    const float* wm   = (const float*)d_in[3];
    const float* bias = (const float*)d_in[4];
    float*       out  = (float*)d_out;

    const int E = in_sizes[1] / 2;
    const int* col = ei + E;

    gemm_kernel<<<(NN + 127) / 128, 256>>>(x, wm);
    median_kernel<<<NN / 2, 128>>>(col, ew, bias, out);
}

// round 4
// speedup vs baseline: 2.7382x; 2.7382x over previous
#include <cuda_runtime.h>
#include <cuda_bf16.h>

#define NN 50000
#define KK 17
#define DIN 128
#define DOUT 64

// Scratch for projected features xp = x @ W : [N, 64] fp32 = 12.8 MB (fits in L2)
__device__ float g_xp[(size_t)NN * DOUT];

// ---------------------------------------------------------------------------
// Kernel 1: xp = x @ W (fp32). At the FFMA floor (~23.4us) — unchanged.
// ---------------------------------------------------------------------------
__global__ void __launch_bounds__(256) gemm_kernel(
    const float* __restrict__ x, const float* __restrict__ wm)
{
    __shared__ float xs[128][32];
    __shared__ float ws[32][64];

    const int tid  = threadIdx.x;
    const int row0 = blockIdx.x * 128;
    const int c0   = (tid & 15) * 4;
    const int r0   = (tid >> 4) * 8;

    float acc[8][4];
#pragma unroll
    for (int i = 0; i < 8; i++)
#pragma unroll
        for (int j = 0; j < 4; j++) acc[i][j] = 0.f;

    for (int k0 = 0; k0 < DIN; k0 += 32) {
#pragma unroll
        for (int i = 0; i < 4; i++) {
            const int f4 = tid + 256 * i;
            const int r  = f4 >> 3;
            const int cc = (f4 & 7) * 4;
            int gr = row0 + r;
            if (gr > NN - 1) gr = NN - 1;
            const float4 v = *(const float4*)(x + (size_t)gr * DIN + k0 + cc);
            *(float4*)&xs[r][cc] = v;
        }
#pragma unroll
        for (int i = 0; i < 2; i++) {
            const int f4 = tid + 256 * i;
            const int r  = f4 >> 4;
            const int cc = (f4 & 15) * 4;
            const float4 v = *(const float4*)(wm + (size_t)(k0 + r) * DOUT + cc);
            *(float4*)&ws[r][cc] = v;
        }
        __syncthreads();

#pragma unroll
        for (int kk = 0; kk < 32; kk += 2) {
            const float4 w0 = *(const float4*)&ws[kk][c0];
            const float4 w1 = *(const float4*)&ws[kk + 1][c0];
#pragma unroll
            for (int i = 0; i < 8; i++) {
                const float2 xv = *(const float2*)&xs[r0 + i][kk];
                acc[i][0] += xv.x * w0.x;
                acc[i][1] += xv.x * w0.y;
                acc[i][2] += xv.x * w0.z;
                acc[i][3] += xv.x * w0.w;
                acc[i][0] += xv.y * w1.x;
                acc[i][1] += xv.y * w1.y;
                acc[i][2] += xv.y * w1.z;
                acc[i][3] += xv.y * w1.w;
            }
        }
        __syncthreads();
    }

#pragma unroll
    for (int i = 0; i < 8; i++) {
        const int gr = row0 + r0 + i;
        if (gr < NN) {
            float4 v;
            v.x = acc[i][0]; v.y = acc[i][1]; v.z = acc[i][2]; v.w = acc[i][3];
            *(float4*)&g_xp[(size_t)gr * DOUT + c0] = v;
        }
    }
}

// ---------------------------------------------------------------------------
// Kernel 2: weighted per-dim median via HARD-CODED truncated Batcher network
// (85 compare-exchanges on named scalars -> no arrays, no spill possible),
// then cumsum walk for first prefix >= 0.5*total.
// One thread per (node, dim); 128-thread blocks = 2 nodes.
// ---------------------------------------------------------------------------

// compare-exchange on (value, weight) pairs: pure lat-4 dataflow ops
#define CE(A, B) do {                                   \
    const bool  sw_   = v##B < v##A;                    \
    const float vmin_ = fminf(v##A, v##B);              \
    const float vmax_ = fmaxf(v##A, v##B);              \
    const float wa_   = sw_ ? w##B : w##A;              \
    const float wb_   = sw_ ? w##A : w##B;              \
    v##A = vmin_;  v##B = vmax_;                        \
    w##A = wa_;    w##B = wb_;                          \
} while (0)

__global__ void __launch_bounds__(128) median_kernel(
    const int*   __restrict__ col,
    const float* __restrict__ ew,
    const float* __restrict__ bias,
    float*       __restrict__ out)
{
    __shared__ float swt[2][KK];
    __shared__ int   soff[2][KK];

    const int tid   = threadIdx.x;
    const int local = tid >> 6;
    const int d     = tid & 63;
    const int node  = blockIdx.x * 2 + local;

    if (d < KK) {
        swt[local][d]  = ew[node * KK + d];
        soff[local][d] = col[node * KK + d] * DOUT;
    }
    __syncthreads();

    const float* __restrict__ xpd = g_xp + d;

#define LOADJ(J) float w##J = swt[local][J]; \
                 float v##J = __ldg(xpd + soff[local][J]);
    LOADJ(0)  LOADJ(1)  LOADJ(2)  LOADJ(3)  LOADJ(4)  LOADJ(5)
    LOADJ(6)  LOADJ(7)  LOADJ(8)  LOADJ(9)  LOADJ(10) LOADJ(11)
    LOADJ(12) LOADJ(13) LOADJ(14) LOADJ(15) LOADJ(16)
#undef LOADJ

    const float total =
        ((w0 + w1) + (w2 + w3)) + ((w4 + w5) + (w6 + w7)) +
        ((w8 + w9) + (w10 + w11)) + ((w12 + w13) + (w14 + w15)) + w16;
    const float hf = 0.5f * total;

    // --- Batcher odd-even mergesort, 32 wires truncated to 17 (85 CEs) ---
    // p=1
    CE(0,1);  CE(2,3);  CE(4,5);  CE(6,7);
    CE(8,9);  CE(10,11); CE(12,13); CE(14,15);
    // p=2, k=2
    CE(0,2);  CE(1,3);  CE(4,6);  CE(5,7);
    CE(8,10); CE(9,11); CE(12,14); CE(13,15);
    // p=2, k=1
    CE(1,2);  CE(5,6);  CE(9,10); CE(13,14);
    // p=4, k=4
    CE(0,4);  CE(1,5);  CE(2,6);  CE(3,7);
    CE(8,12); CE(9,13); CE(10,14); CE(11,15);
    // p=4, k=2
    CE(2,4);  CE(3,5);  CE(10,12); CE(11,13);
    // p=4, k=1
    CE(1,2);  CE(3,4);  CE(5,6);  CE(9,10); CE(11,12); CE(13,14);
    // p=8, k=8
    CE(0,8);  CE(1,9);  CE(2,10); CE(3,11);
    CE(4,12); CE(5,13); CE(6,14); CE(7,15);
    // p=8, k=4
    CE(4,8);  CE(5,9);  CE(6,10); CE(7,11);
    // p=8, k=2
    CE(2,4);  CE(3,5);  CE(6,8);  CE(7,9); CE(10,12); CE(11,13);
    // p=8, k=1
    CE(1,2);  CE(3,4);  CE(5,6);  CE(7,8); CE(9,10); CE(11,12); CE(13,14);
    // p=16, k=16
    CE(0,16);
    // p=16, k=8
    CE(8,16);
    // p=16, k=4
    CE(4,8);  CE(5,9);  CE(6,10); CE(7,11); CE(12,16);
    // p=16, k=2
    CE(2,4);  CE(3,5);  CE(6,8);  CE(7,9); CE(10,12); CE(11,13); CE(14,16);
    // p=16, k=1
    CE(1,2);  CE(3,4);  CE(5,6);  CE(7,8);
    CE(9,10); CE(11,12); CE(13,14); CE(15,16);

    // --- cumsum walk: first sorted element with cumulative weight >= hf ---
    float cum = w0;
    float med = v0;
#define STEP(J) med = (cum < hf) ? v##J : med; cum += w##J;
    STEP(1)  STEP(2)  STEP(3)  STEP(4)  STEP(5)  STEP(6)  STEP(7)  STEP(8)
    STEP(9)  STEP(10) STEP(11) STEP(12) STEP(13) STEP(14) STEP(15) STEP(16)
#undef STEP

    out[(size_t)node * DOUT + d] = total * med + __ldg(&bias[d]);
}

// ---------------------------------------------------------------------------
// Inputs: x[N,128] f32, edge_index[2,E] i32, edge_weight[E] f32,
//         weight[128,64] f32, bias[64] f32. Output: [N,64] f32.
// ---------------------------------------------------------------------------
extern "C" void kernel_launch(void* const* d_in, const int* in_sizes, int n_in,
                              void* d_out, int out_size)
{
    const float* x    = (const float*)d_in[0];
    const int*   ei   = (const int*)  d_in[1];
    const float* ew   = (const float*)d_in[2];
    const float* wm   = (const float*)d_in[3];
    const float* bias = (const float*)d_in[4];
    float*       out  = (float*)d_out;

    const int E = in_sizes[1] / 2;
    const int* col = ei + E;

    gemm_kernel<<<(NN + 127) / 128, 256>>>(x, wm);
    median_kernel<<<NN / 2, 128>>>(col, ew, bias, out);
}

// round 5
// speedup vs baseline: 2.8623x; 1.0453x over previous
#include <cuda_runtime.h>
#include <cuda_bf16.h>

#define NN 50000
#define KK 17
#define DIN 128
#define DOUT 64

// Scratch for projected features xp = x @ W : [N, 64] fp32 = 12.8 MB (fits in L2)
__device__ float g_xp[(size_t)NN * DOUT];

// ---------------------------------------------------------------------------
// f32x2 helpers (Blackwell double-rate FP32; SASS FFMA2)
// ---------------------------------------------------------------------------
__device__ __forceinline__ unsigned long long lds64v(unsigned a) {
    unsigned long long v;
    asm volatile("ld.shared.b64 %0, [%1];" : "=l"(v) : "r"(a));
    return v;
}
__device__ __forceinline__ void fma2(unsigned long long& d,
                                     unsigned long long a,
                                     unsigned long long b) {
    asm("fma.rn.f32x2 %0, %1, %2, %0;" : "+l"(d) : "l"(a), "l"(b));
}
__device__ __forceinline__ float pairsum(unsigned long long a) {
    const float lo = __uint_as_float((unsigned)(a & 0xffffffffull));
    const float hi = __uint_as_float((unsigned)(a >> 32));
    return lo + hi;
}

// ---------------------------------------------------------------------------
// Kernel 1: xp = x @ W via packed FFMA2. Tile M=64 x N=64, full K in smem.
// Each acc holds {even-k partial, odd-k partial}; summed at the end.
// x pair {x[r][k],x[r][k+1]} : contiguous LDS.64 (row-major xs).
// w pair {w[k][c],w[k+1][c]} : contiguous LDS.64 in once-staged transposed wsT.
// Thread map: r0 = tid&15 (rows r0+16i), c0 = (tid>>4)*4.
//   -> w reads broadcast (conflict-free), x reads stride-2 banks (conflict-free
//      with row stride 130 words).
// ---------------------------------------------------------------------------
#define GSTRIDE 130   // words per row for both xs and wsT (even: 8B aligned)

__global__ void __launch_bounds__(256) gemm_kernel(
    const float* __restrict__ x, const float* __restrict__ wm)
{
    extern __shared__ float smem[];
    float* xs  = smem;                 // [64][130]
    float* wsT = smem + 64 * GSTRIDE;  // [64][130]

    const int tid = threadIdx.x;
    const int r0  = tid & 15;
    const int c0  = (tid >> 4) * 4;

    // --- stage wsT once per block: wm[k][c] -> wsT[c][k] ---
#pragma unroll
    for (int i = 0; i < 8; i++) {
        const int idx = tid + 256 * i;        // 0..2047 float4s
        const int k   = idx >> 4;             // 0..127
        const int c   = (idx & 15) * 4;       // 0..60
        const float4 v = *(const float4*)(wm + (size_t)k * DOUT + c);
        wsT[(c + 0) * GSTRIDE + k] = v.x;
        wsT[(c + 1) * GSTRIDE + k] = v.y;
        wsT[(c + 2) * GSTRIDE + k] = v.z;
        wsT[(c + 3) * GSTRIDE + k] = v.w;
    }

    const unsigned xs_b = (unsigned)__cvta_generic_to_shared(xs);
    const unsigned ws_b = (unsigned)__cvta_generic_to_shared(wsT);
    const unsigned xa   = xs_b + (unsigned)(r0 * GSTRIDE) * 4u;
    const unsigned wa   = ws_b + (unsigned)(c0 * GSTRIDE) * 4u;

    for (int t = 0; t < 2; t++) {
        const int row0 = (blockIdx.x * 2 + t) * 64;

        __syncthreads();  // previous tile fully consumed before restaging
        // --- stage xs: x[row0+r][k] -> xs[r][k], one warp per row per i ---
#pragma unroll
        for (int i = 0; i < 8; i++) {
            const int idx = tid + 256 * i;    // 0..2047 float4s
            const int r   = idx >> 5;         // 0..63
            const int cc  = (idx & 31) * 4;   // 0..124
            int gr = row0 + r;
            if (gr > NN - 1) gr = NN - 1;
            const float4 v = *(const float4*)(x + (size_t)gr * DIN + cc);
            *(float2*)&xs[r * GSTRIDE + cc]     = make_float2(v.x, v.y);
            *(float2*)&xs[r * GSTRIDE + cc + 2] = make_float2(v.z, v.w);
        }
        __syncthreads();

        unsigned long long acc[4][4];
#pragma unroll
        for (int i = 0; i < 4; i++)
#pragma unroll
            for (int j = 0; j < 4; j++) acc[i][j] = 0ull;

#pragma unroll 8
        for (int kk = 0; kk < DIN; kk += 2) {
            unsigned long long wv[4], xv[4];
#pragma unroll
            for (int j = 0; j < 4; j++)
                wv[j] = lds64v(wa + (unsigned)(j * GSTRIDE + kk) * 4u);
#pragma unroll
            for (int i = 0; i < 4; i++)
                xv[i] = lds64v(xa + (unsigned)(i * 16 * GSTRIDE + kk) * 4u);
#pragma unroll
            for (int i = 0; i < 4; i++)
#pragma unroll
                for (int j = 0; j < 4; j++) fma2(acc[i][j], xv[i], wv[j]);
        }

#pragma unroll
        for (int i = 0; i < 4; i++) {
            const int gr = row0 + r0 + 16 * i;
            if (gr < NN) {
                float4 v;
                v.x = pairsum(acc[i][0]);
                v.y = pairsum(acc[i][1]);
                v.z = pairsum(acc[i][2]);
                v.w = pairsum(acc[i][3]);
                *(float4*)&g_xp[(size_t)gr * DOUT + c0] = v;
            }
        }
    }
}

// ---------------------------------------------------------------------------
// Kernel 2: weighted per-dim median via hard-coded truncated Batcher network,
// with pipe-balanced compare-exchange forms:
//   CEA: all-alu   (FSETP + 2 FMNMX + 2 FSEL)            = 5 alu
//   CEF: fma-heavy (FSETP + FSEL-ind + 2 FADD + 4 FFMA)  = 2 alu + 6 fma
// Mix 40 A : 45 C -> alu ~290, fma ~270 per thread (both pipes ~full).
// ---------------------------------------------------------------------------
#define CEA(A, B) do {                                  \
    const bool  p_  = v##B < v##A;                      \
    const float vl_ = fminf(v##A, v##B);                \
    const float vh_ = fmaxf(v##A, v##B);                \
    const float wl_ = p_ ? w##B : w##A;                 \
    const float wh_ = p_ ? w##A : w##B;                 \
    v##A = vl_;  v##B = vh_;  w##A = wl_;  w##B = wh_;  \
} while (0)

#define CEF(A, B) do {                                  \
    const float ind_ = (v##B < v##A) ? 1.0f : 0.0f;     \
    const float dv_  = v##A - v##B;                     \
    const float dw_  = w##A - w##B;                     \
    const float vl_  = __fmaf_rn(-ind_, dv_, v##A);     \
    const float vh_  = __fmaf_rn( ind_, dv_, v##B);     \
    const float wl_  = __fmaf_rn(-ind_, dw_, w##A);     \
    const float wh_  = __fmaf_rn( ind_, dw_, w##B);     \
    v##A = vl_;  v##B = vh_;  w##A = wl_;  w##B = wh_;  \
} while (0)

__global__ void __launch_bounds__(256) median_kernel(
    const int*   __restrict__ col,
    const float* __restrict__ ew,
    const float* __restrict__ bias,
    float*       __restrict__ out)
{
    __shared__ float swt[4][KK];
    __shared__ int   soff[4][KK];

    const int tid   = threadIdx.x;
    const int local = tid >> 6;
    const int d     = tid & 63;
    const int node  = blockIdx.x * 4 + local;

    if (d < KK) {
        swt[local][d]  = ew[node * KK + d];
        soff[local][d] = col[node * KK + d] * DOUT;
    }
    __syncthreads();

    const float* __restrict__ xpd = g_xp + d;

#define LOADJ(J) float w##J = swt[local][J]; \
                 float v##J = __ldg(xpd + soff[local][J]);
    LOADJ(0)  LOADJ(1)  LOADJ(2)  LOADJ(3)  LOADJ(4)  LOADJ(5)
    LOADJ(6)  LOADJ(7)  LOADJ(8)  LOADJ(9)  LOADJ(10) LOADJ(11)
    LOADJ(12) LOADJ(13) LOADJ(14) LOADJ(15) LOADJ(16)
#undef LOADJ

    const float total =
        ((w0 + w1) + (w2 + w3)) + ((w4 + w5) + (w6 + w7)) +
        ((w8 + w9) + (w10 + w11)) + ((w12 + w13) + (w14 + w15)) + w16;
    const float hf = 0.5f * total;

    // Truncated Batcher odd-even mergesort (85 CEs), forms per pos%9<4 -> A.
    // L1
    CEA(0,1);  CEA(2,3);  CEA(4,5);  CEA(6,7);
    CEF(8,9);  CEF(10,11); CEF(12,13); CEF(14,15);
    // L2
    CEF(0,2);  CEA(1,3);  CEA(4,6);  CEA(5,7);
    CEA(8,10); CEF(9,11); CEF(12,14); CEF(13,15);
    // L3
    CEF(1,2);  CEF(5,6);  CEA(9,10); CEA(13,14);
    // L4
    CEA(0,4);  CEA(1,5);  CEF(2,6);  CEF(3,7);
    CEF(8,12); CEF(9,13); CEF(10,14); CEA(11,15);
    // L5
    CEA(2,4);  CEA(3,5);  CEA(10,12); CEF(11,13);
    // L6
    CEF(1,2);  CEF(3,4);  CEF(5,6);  CEF(9,10); CEA(11,12); CEA(13,14);
    // L7
    CEA(0,8);  CEA(1,9);  CEF(2,10); CEF(3,11);
    CEF(4,12); CEF(5,13); CEF(6,14); CEA(7,15);
    // L8
    CEA(4,8);  CEA(5,9);  CEA(6,10); CEF(7,11);
    // L9
    CEF(2,4);  CEF(3,5);  CEF(6,8);  CEF(7,9); CEA(10,12); CEA(11,13);
    // L10
    CEA(1,2);  CEA(3,4);  CEF(5,6);  CEF(7,8);
    CEF(9,10); CEF(11,12); CEF(13,14);
    // L11, L12
    CEA(0,16);
    CEA(8,16);
    // L13
    CEA(4,8);  CEA(5,9);  CEF(6,10); CEF(7,11); CEF(12,16);
    // L14
    CEF(2,4);  CEF(3,5);  CEA(6,8);  CEA(7,9);
    CEA(10,12); CEA(11,13); CEF(14,16);
    // L15
    CEF(1,2);  CEF(3,4);  CEF(5,6);  CEF(7,8);
    CEA(9,10); CEA(11,12); CEA(13,14); CEA(15,16);

    // cumsum walk: first sorted element with cumulative weight >= hf.
    float cum = w0;
    float med = v0;
#define STEP(J) med = (cum < hf) ? v##J : med; cum += w##J;
    STEP(1)  STEP(2)  STEP(3)  STEP(4)  STEP(5)  STEP(6)  STEP(7)  STEP(8)
    STEP(9)  STEP(10) STEP(11) STEP(12) STEP(13) STEP(14) STEP(15) STEP(16)
#undef STEP

    out[(size_t)node * DOUT + d] = total * med + __ldg(&bias[d]);
}

// ---------------------------------------------------------------------------
// Inputs: x[N,128] f32, edge_index[2,E] i32, edge_weight[E] f32,
//         weight[128,64] f32, bias[64] f32. Output: [N,64] f32.
// ---------------------------------------------------------------------------
extern "C" void kernel_launch(void* const* d_in, const int* in_sizes, int n_in,
                              void* d_out, int out_size)
{
    const float* x    = (const float*)d_in[0];
    const int*   ei   = (const int*)  d_in[1];
    const float* ew   = (const float*)d_in[2];
    const float* wm   = (const float*)d_in[3];
    const float* bias = (const float*)d_in[4];
    float*       out  = (float*)d_out;

    const int E = in_sizes[1] / 2;
    const int* col = ei + E;

    const int smem_bytes = 2 * 64 * GSTRIDE * 4;  // 66560
    static bool attr_set = false;
    if (!attr_set) {
        cudaFuncSetAttribute(gemm_kernel,
                             cudaFuncAttributeMaxDynamicSharedMemorySize,
                             smem_bytes);
        attr_set = true;
    }

    // 782 M-tiles of 64 rows, 2 per block
    gemm_kernel<<<391, 256, smem_bytes>>>(x, wm);
    median_kernel<<<NN / 4, 256>>>(col, ew, bias, out);
}

// round 6
// speedup vs baseline: 3.7389x; 1.3063x over previous
#include <cuda_runtime.h>
#include <cuda_bf16.h>

#define NN 50000
#define KK 17
#define DIN 128
#define DOUT 64

// Scratch for projected features xp = x @ W : [N, 64] fp32 = 12.8 MB (fits in L2)
__device__ float g_xp[(size_t)NN * DOUT];

// ---------------------------------------------------------------------------
// Kernel 1: xp = x @ W (fp32). R4 version — proven 21.2us.
// ---------------------------------------------------------------------------
__global__ void __launch_bounds__(256) gemm_kernel(
    const float* __restrict__ x, const float* __restrict__ wm)
{
    __shared__ float xs[128][32];
    __shared__ float ws[32][64];

    const int tid  = threadIdx.x;
    const int row0 = blockIdx.x * 128;
    const int c0   = (tid & 15) * 4;
    const int r0   = (tid >> 4) * 8;

    float acc[8][4];
#pragma unroll
    for (int i = 0; i < 8; i++)
#pragma unroll
        for (int j = 0; j < 4; j++) acc[i][j] = 0.f;

    for (int k0 = 0; k0 < DIN; k0 += 32) {
#pragma unroll
        for (int i = 0; i < 4; i++) {
            const int f4 = tid + 256 * i;
            const int r  = f4 >> 3;
            const int cc = (f4 & 7) * 4;
            int gr = row0 + r;
            if (gr > NN - 1) gr = NN - 1;
            const float4 v = *(const float4*)(x + (size_t)gr * DIN + k0 + cc);
            *(float4*)&xs[r][cc] = v;
        }
#pragma unroll
        for (int i = 0; i < 2; i++) {
            const int f4 = tid + 256 * i;
            const int r  = f4 >> 4;
            const int cc = (f4 & 15) * 4;
            const float4 v = *(const float4*)(wm + (size_t)(k0 + r) * DOUT + cc);
            *(float4*)&ws[r][cc] = v;
        }
        __syncthreads();

#pragma unroll
        for (int kk = 0; kk < 32; kk += 2) {
            const float4 w0 = *(const float4*)&ws[kk][c0];
            const float4 w1 = *(const float4*)&ws[kk + 1][c0];
#pragma unroll
            for (int i = 0; i < 8; i++) {
                const float2 xv = *(const float2*)&xs[r0 + i][kk];
                acc[i][0] += xv.x * w0.x;
                acc[i][1] += xv.x * w0.y;
                acc[i][2] += xv.x * w0.z;
                acc[i][3] += xv.x * w0.w;
                acc[i][0] += xv.y * w1.x;
                acc[i][1] += xv.y * w1.y;
                acc[i][2] += xv.y * w1.z;
                acc[i][3] += xv.y * w1.w;
            }
        }
        __syncthreads();
    }

#pragma unroll
    for (int i = 0; i < 8; i++) {
        const int gr = row0 + r0 + i;
        if (gr < NN) {
            float4 v;
            v.x = acc[i][0]; v.y = acc[i][1]; v.z = acc[i][2]; v.w = acc[i][3];
            *(float4*)&g_xp[(size_t)gr * DOUT + c0] = v;
        }
    }
}

// ---------------------------------------------------------------------------
// Kernel 2: weighted per-dim median.
// Keys = value with low-5 mantissa bits replaced by element index:
//   key_j = (bits(v_j) & ~31) | j         (always-distinct, order-preserving
//                                          up to a <=31-ulp perturbation)
// Sort 17 keys with the truncated Batcher network using ONLY FMNMX (2 alu/CE,
// bit-exact so the index rides along). Then recover sorted weights by index
// from smem and do the cumsum walk. Median value = key with index bits masked.
// ---------------------------------------------------------------------------
#define CE(A, B) do {                      \
    const float ka_ = k##A, kb_ = k##B;    \
    k##A = fminf(ka_, kb_);                \
    k##B = fmaxf(ka_, kb_);                \
} while (0)

__global__ void __launch_bounds__(256) median_kernel(
    const int*   __restrict__ col,
    const float* __restrict__ ew,
    const float* __restrict__ bias,
    float*       __restrict__ out)
{
    __shared__ float swt[4][KK];
    __shared__ int   soff[4][KK];

    const int tid   = threadIdx.x;
    const int local = tid >> 6;
    const int d     = tid & 63;
    const int node  = blockIdx.x * 4 + local;

    if (d < KK) {
        swt[local][d]  = ew[node * KK + d];
        soff[local][d] = col[node * KK + d] * DOUT;
    }
    __syncthreads();

    const float* __restrict__ xpd = g_xp + d;

    // load values and embed index into low 5 bits (single LOP3 each)
#define LOADJ(J) float k##J = __uint_as_float(                                 \
        (__float_as_uint(__ldg(xpd + soff[local][J])) & 0xFFFFFFE0u) |         \
        (unsigned)J);
    LOADJ(0)  LOADJ(1)  LOADJ(2)  LOADJ(3)  LOADJ(4)  LOADJ(5)
    LOADJ(6)  LOADJ(7)  LOADJ(8)  LOADJ(9)  LOADJ(10) LOADJ(11)
    LOADJ(12) LOADJ(13) LOADJ(14) LOADJ(15) LOADJ(16)
#undef LOADJ

    // total weight (fma pipe)
    const float* wl = swt[local];
    const float total =
        ((wl[0] + wl[1]) + (wl[2] + wl[3])) + ((wl[4] + wl[5]) + (wl[6] + wl[7])) +
        ((wl[8] + wl[9]) + (wl[10] + wl[11])) +
        ((wl[12] + wl[13]) + (wl[14] + wl[15])) + wl[16];
    const float hf = 0.5f * total;

    // --- truncated Batcher odd-even mergesort, 85 CEs, 2 FMNMX each ---
    // p=1
    CE(0,1);  CE(2,3);  CE(4,5);  CE(6,7);
    CE(8,9);  CE(10,11); CE(12,13); CE(14,15);
    // p=2, k=2
    CE(0,2);  CE(1,3);  CE(4,6);  CE(5,7);
    CE(8,10); CE(9,11); CE(12,14); CE(13,15);
    // p=2, k=1
    CE(1,2);  CE(5,6);  CE(9,10); CE(13,14);
    // p=4, k=4
    CE(0,4);  CE(1,5);  CE(2,6);  CE(3,7);
    CE(8,12); CE(9,13); CE(10,14); CE(11,15);
    // p=4, k=2
    CE(2,4);  CE(3,5);  CE(10,12); CE(11,13);
    // p=4, k=1
    CE(1,2);  CE(3,4);  CE(5,6);  CE(9,10); CE(11,12); CE(13,14);
    // p=8, k=8
    CE(0,8);  CE(1,9);  CE(2,10); CE(3,11);
    CE(4,12); CE(5,13); CE(6,14); CE(7,15);
    // p=8, k=4
    CE(4,8);  CE(5,9);  CE(6,10); CE(7,11);
    // p=8, k=2
    CE(2,4);  CE(3,5);  CE(6,8);  CE(7,9); CE(10,12); CE(11,13);
    // p=8, k=1
    CE(1,2);  CE(3,4);  CE(5,6);  CE(7,8); CE(9,10); CE(11,12); CE(13,14);
    // p=16
    CE(0,16);
    CE(8,16);
    CE(4,8);  CE(5,9);  CE(6,10); CE(7,11); CE(12,16);
    CE(2,4);  CE(3,5);  CE(6,8);  CE(7,9); CE(10,12); CE(11,13); CE(14,16);
    CE(1,2);  CE(3,4);  CE(5,6);  CE(7,8);
    CE(9,10); CE(11,12); CE(13,14); CE(15,16);

    // --- recover sorted weights by embedded index (LOP3 + LDS each) ---
#define SWJ(J) const float sw##J = wl[__float_as_uint(k##J) & 31u];
    SWJ(0)  SWJ(1)  SWJ(2)  SWJ(3)  SWJ(4)  SWJ(5)  SWJ(6)  SWJ(7)  SWJ(8)
    SWJ(9)  SWJ(10) SWJ(11) SWJ(12) SWJ(13) SWJ(14) SWJ(15) SWJ(16)
#undef SWJ

    // --- cumsum walk: first sorted element with cumulative weight >= hf ---
    float cum = sw0;
    float med = k0;
#define STEP(J) med = (cum < hf) ? k##J : med; cum += sw##J;
    STEP(1)  STEP(2)  STEP(3)  STEP(4)  STEP(5)  STEP(6)  STEP(7)  STEP(8)
    STEP(9)  STEP(10) STEP(11) STEP(12) STEP(13) STEP(14) STEP(15) STEP(16)
#undef STEP

    // strip index bits from the median value
    const float medv = __uint_as_float(__float_as_uint(med) & 0xFFFFFFE0u);

    out[(size_t)node * DOUT + d] = total * medv + __ldg(&bias[d]);
}

// ---------------------------------------------------------------------------
// Inputs: x[N,128] f32, edge_index[2,E] i32, edge_weight[E] f32,
//         weight[128,64] f32, bias[64] f32. Output: [N,64] f32.
// ---------------------------------------------------------------------------
extern "C" void kernel_launch(void* const* d_in, const int* in_sizes, int n_in,
                              void* d_out, int out_size)
{
    const float* x    = (const float*)d_in[0];
    const int*   ei   = (const int*)  d_in[1];
    const float* ew   = (const float*)d_in[2];
    const float* wm   = (const float*)d_in[3];
    const float* bias = (const float*)d_in[4];
    float*       out  = (float*)d_out;

    const int E = in_sizes[1] / 2;
    const int* col = ei + E;

    gemm_kernel<<<(NN + 127) / 128, 256>>>(x, wm);
    median_kernel<<<NN / 4, 256>>>(col, ew, bias, out);
}